// round 15
// baseline (speedup 1.0000x reference)
#include <cuda_runtime.h>
#include <cuda_bf16.h>
#include <math.h>
#include <stdint.h>

// ---------------- problem constants ----------------
#define BB   8
#define NN_  1024
#define DD   512
#define HH   8
#define DHH  64
#define DEE  2048
#define ROWS (BB*NN_)        // 8192
#define QKVW 5120

// ---------------- scratch (device globals) ----------------
__device__ __align__(128) __nv_bfloat16 g_h_e   [ROWS*3*DD];           // A-format LN0 out
__device__ __align__(128) __nv_bfloat16 g_wqk_e [3*DD*1024];           // B-format W_q|W_k
__device__ __align__(128) __nv_bfloat16 g_wv_ae [HH*DD*3*DD];          // A-format W_v per head
__device__ __align__(128) __nv_bfloat16 g_wmrg_e[HH*3*DD*DD];          // B-format W_merge per head
__device__ __align__(128) __nv_bfloat16 g_wc_e  [HH*3*DD*DD];          // B-format Wc = Wv@Wmrg per head
__device__ __align__(128) __nv_bfloat16 g_q_e   [ROWS*3*DD];           // A-format q
__device__ __align__(128) __nv_bfloat16 g_k_e   [BB*HH*DHH*3*NN_];     // A-format k^T (scaled)
__device__ __align__(128) __nv_bfloat16 g_kh_e  [BB*HH*DHH*3*DD];      // A-format kh = k^T h
__device__ __align__(128) __nv_bfloat16 g_m2_e  [BB*3*DD*DD];          // B-format M2cat per batch
__device__ __align__(128) float         g_x1    [ROWS*DD];
__device__ __align__(128) __nv_bfloat16 g_xn_e  [ROWS*3*DD];
__device__ __align__(128) __nv_bfloat16 g_wff1_e[3*DD*DEE];
__device__ __align__(128) float         g_f     [(size_t)ROWS*DEE];
__device__ __align__(128) __nv_bfloat16 g_g_e   [(size_t)ROWS*3*DEE];
__device__ __align__(128) __nv_bfloat16 g_wff2_e[3*DEE*DD];

// ---------------- helpers ----------------
__device__ __forceinline__ uint32_t smem_to_u32(const void* p) {
    uint32_t a;
    asm("{ .reg .u64 t; cvta.to.shared.u64 t, %1; cvt.u32.u64 %0, t; }" : "=r"(a) : "l"(p));
    return a;
}
#define SWZ(b) ((uint32_t)(b) ^ ((((uint32_t)(b)) >> 3) & 0x70))

#define CP_ASYNC16(dst, src) \
    asm volatile("cp.async.cg.shared.global [%0], [%1], 16;" :: "r"(dst), "l"(src) : "memory")
#define CP_COMMIT() asm volatile("cp.async.commit_group;" ::: "memory")
#define CP_WAIT1()  asm volatile("cp.async.wait_group 1;" ::: "memory")
#define CP_WAIT0()  asm volatile("cp.async.wait_group 0;" ::: "memory")

#define LDMATRIX_X4(r, addr) \
    asm volatile("ldmatrix.sync.aligned.m8n8.x4.shared.b16 {%0,%1,%2,%3}, [%4];" \
        : "=r"((r)[0]), "=r"((r)[1]), "=r"((r)[2]), "=r"((r)[3]) : "r"(addr))
#define LDMATRIX_X4_T(r, addr) \
    asm volatile("ldmatrix.sync.aligned.m8n8.x4.trans.shared.b16 {%0,%1,%2,%3}, [%4];" \
        : "=r"((r)[0]), "=r"((r)[1]), "=r"((r)[2]), "=r"((r)[3]) : "r"(addr))

#define MMA16816(c, a, b0v, b1v) \
    asm volatile("mma.sync.aligned.m16n8k16.row.col.f32.bf16.bf16.f32 " \
        "{%0,%1,%2,%3}, {%4,%5,%6,%7}, {%8,%9}, {%0,%1,%2,%3};" \
        : "+f"((c)[0]), "+f"((c)[1]), "+f"((c)[2]), "+f"((c)[3]) \
        : "r"((a)[0]), "r"((a)[1]), "r"((a)[2]), "r"((a)[3]), "r"(b0v), "r"(b1v))

__device__ __forceinline__ void split2(float v, __nv_bfloat16& h, __nv_bfloat16& l) {
    h = __float2bfloat16(v);
    l = __float2bfloat16(v - __bfloat162float(h));
}
__device__ __forceinline__ void st_b2(__nv_bfloat16* p, __nv_bfloat16 a, __nv_bfloat16 b) {
    __nv_bfloat162 t; t.x = a; t.y = b;
    *reinterpret_cast<__nv_bfloat162*>(p) = t;
}

// epilogue modes
#define EPI_F32 0
#define EPI_QK  1
#define EPI_KH  2
#define EPI_M2  3
#define EPI_WC  4

// ---------------- bf16 MMA GEMM ----------------
// BM in {128,64}; BN=128; BK=64; 8 warps. z = blockIdx.z; B batch idx = z%bmod or z/bdiv.
// BRM: remap B-source reads to A-format h_e layout ([hi|lo|hi] rows of 1536,
//      k-row kk -> h_e[(kk&1023)][ (kk>>10)==2 ? 512+d : d ]).
template<int BM, int EPI, int BRM>
__global__ void __launch_bounds__(256, 2)
tgemm(const __nv_bfloat16* __restrict__ A, const __nv_bfloat16* __restrict__ B,
      float* __restrict__ C, const float* __restrict__ bias,
      const float* __restrict__ Res, const float* __restrict__ scaleptr,
      __nv_bfloat16* __restrict__ O0, __nv_bfloat16* __restrict__ O1,
      int Kp, int lda, int ldb, int ldc,
      long bA, long bB, long bC, int bmod, int bdiv)
{
    constexpr int WMS  = BM / 32;
    constexpr int WNT  = 128 / (8 / WMS);
    constexpr int NG   = WNT / 16;
    constexpr int NT   = 2 * NG;
    constexpr int ABUF = BM * 128;

    extern __shared__ __align__(1024) char smem[];
    const uint32_t sbase = smem_to_u32(smem);
    const uint32_t sA = sbase, sB = sbase + 2 * ABUF;

    int tid = threadIdx.x, lane = tid & 31, wid = tid >> 5;
    int wm = wid % WMS, wn = wid / WMS;
    int z = blockIdx.z;
    int zB = bmod ? (z % bmod) : (bdiv ? (z / bdiv) : z);
    A += (size_t)z * bA;
    B += (size_t)zB * bB;
    int m0 = blockIdx.y * BM, n0 = blockIdx.x * 128;

    float acc[2][NT][4];
#pragma unroll
    for (int i = 0; i < 2; i++)
#pragma unroll
        for (int j = 0; j < NT; j++)
#pragma unroll
            for (int k = 0; k < 4; k++) acc[i][j][k] = 0.f;

    int nch = Kp >> 6;
    const int a_r = tid >> 3, a_c = tid & 7;

    auto load_chunk = [&](int i) {
        int buf = i & 1;
        int k0 = i << 6;
        uint32_t abuf = sA + buf * ABUF;
        uint32_t bbuf = sB + buf * 16384;
#pragma unroll
        for (int it = 0; it < BM / 32; it++) {
            int r = a_r + it * 32;
            const __nv_bfloat16* src = A + (size_t)(m0 + r) * lda + k0 + a_c * 8;
            CP_ASYNC16(abuf + SWZ(r * 128 + a_c * 16), src);
        }
#pragma unroll
        for (int it = 0; it < 4; it++) {
            int idx = tid + it * 256;
            int sub = idx >> 9, r = (idx >> 3) & 63, c = idx & 7;
            const __nv_bfloat16* src;
            if (BRM) {
                int kk = k0 + r;
                src = B + (size_t)(kk & 1023) * 1536 + ((kk >> 10) == 2 ? 512 : 0)
                        + n0 + sub * 64 + c * 8;
            } else {
                src = B + (size_t)(k0 + r) * ldb + n0 + sub * 64 + c * 8;
            }
            CP_ASYNC16(bbuf + sub * 8192 + SWZ(r * 128 + c * 16), src);
        }
        CP_COMMIT();
    };

    load_chunk(0);

    const int colsub = (wn * WNT) & 63;
    const int bsub   = (wn * WNT) >> 6;

    for (int i = 0; i < nch; i++) {
        if (i + 1 < nch) { load_chunk(i + 1); CP_WAIT1(); }
        else             { CP_WAIT0(); }
        __syncthreads();

        uint32_t abuf = sA + (i & 1) * ABUF;
        uint32_t bbuf = sB + (i & 1) * 16384 + bsub * 8192;

#pragma unroll
        for (int ks = 0; ks < 4; ks++) {
            uint32_t a[2][4];
#pragma unroll
            for (int mt = 0; mt < 2; mt++) {
                uint32_t addr = abuf +
                    SWZ((wm * 32 + mt * 16 + (lane & 15)) * 128 + ks * 32 + (lane >> 4) * 16);
                LDMATRIX_X4(a[mt], addr);
            }
            int krow = ks * 16 + (lane & 7) + ((lane >> 3) & 1) * 8;
#pragma unroll
            for (int ng = 0; ng < NG; ng++) {
                uint32_t b[4];
                int ncol = colsub + ng * 16 + (lane >> 4) * 8;
                LDMATRIX_X4_T(b, bbuf + SWZ(krow * 128 + ncol * 2));
                MMA16816(acc[0][ng * 2],     a[0], b[0], b[1]);
                MMA16816(acc[0][ng * 2 + 1], a[0], b[2], b[3]);
                MMA16816(acc[1][ng * 2],     a[1], b[0], b[1]);
                MMA16816(acc[1][ng * 2 + 1], a[1], b[2], b[3]);
            }
        }
        __syncthreads();
    }

    // ---------------- epilogue ----------------
    float rs = 1.f;
    if (EPI == EPI_QK) rs = rsqrtf(__ldg(scaleptr));

    int mbase = m0 + wm * 32 + (lane >> 2);
    int nbase = n0 + wn * WNT + (lane & 3) * 2;

#pragma unroll
    for (int mt = 0; mt < 2; mt++) {
#pragma unroll
        for (int nt = 0; nt < NT; nt++) {
            int c0 = nbase + nt * 8;
            float b0 = 0.f, b1 = 0.f;
            if (bias) { b0 = bias[c0]; b1 = bias[c0 + 1]; }
            float v00 = acc[mt][nt][0] + b0, v01 = acc[mt][nt][1] + b1;
            float v10 = acc[mt][nt][2] + b0, v11 = acc[mt][nt][3] + b1;
            int rA = mbase + mt * 16;

            if (EPI == EPI_F32) {
                if (Res) {
                    const float* R = Res + (size_t)z * bC;
                    v00 += R[(size_t)rA * ldc + c0];
                    v01 += R[(size_t)rA * ldc + c0 + 1];
                    v10 += R[(size_t)(rA + 8) * ldc + c0];
                    v11 += R[(size_t)(rA + 8) * ldc + c0 + 1];
                }
                float* Cz = C + (size_t)z * bC;
                *(float2*)&Cz[(size_t)rA * ldc + c0]       = make_float2(v00, v01);
                *(float2*)&Cz[(size_t)(rA + 8) * ldc + c0] = make_float2(v10, v11);
            } else if (EPI == EPI_QK) {
#pragma unroll
                for (int hrow = 0; hrow < 2; hrow++) {
                    int row = rA + hrow * 8;
                    float u0 = hrow ? v10 : v00;
                    float u1 = hrow ? v11 : v01;
                    if (c0 < 512) {
                        __nv_bfloat16 h0, l0, h1, l1;
                        split2(u0, h0, l0); split2(u1, h1, l1);
                        __nv_bfloat16* p = O0 + (size_t)row * 1536 + c0;
                        st_b2(p, h0, h1);
                        st_b2(p + 512, l0, l1);
                        st_b2(p + 1024, h0, h1);
                    } else {
                        u0 *= rs; u1 *= rs;
                        int cc = c0 - 512;
                        int hh = cc >> 6, m = cc & 63;
                        int b = row >> 10, ns = row & 1023;
                        __nv_bfloat16 h0, l0, h1, l1;
                        split2(u0, h0, l0); split2(u1, h1, l1);
                        __nv_bfloat16* p0 = O1 + ((size_t)(b * 8 + hh) * 64 + m) * 3072 + ns;
                        __nv_bfloat16* p1 = p0 + 3072;
                        p0[0] = h0; p0[1024] = l0; p0[2048] = h0;
                        p1[0] = h1; p1[1024] = l1; p1[2048] = h1;
                    }
                }
            } else if (EPI == EPI_KH) {
#pragma unroll
                for (int hrow = 0; hrow < 2; hrow++) {
                    int row = rA + hrow * 8;
                    float u0 = hrow ? v10 : v00;
                    float u1 = hrow ? v11 : v01;
                    __nv_bfloat16 h0, l0, h1, l1;
                    split2(u0, h0, l0); split2(u1, h1, l1);
                    __nv_bfloat16* p = O0 + ((size_t)z * 64 + row) * 1536 + c0;
                    st_b2(p, h0, h1);
                    st_b2(p + 512, l0, l1);
                    st_b2(p + 1024, h0, h1);
                }
            } else if (EPI == EPI_M2) {
                int b = z >> 3, h = z & 7;
#pragma unroll
                for (int hrow = 0; hrow < 2; hrow++) {
                    int row = rA + hrow * 8;
                    float u0 = hrow ? v10 : v00;
                    float u1 = hrow ? v11 : v01;
                    __nv_bfloat16 h0, l0, h1, l1;
                    split2(u0, h0, l0); split2(u1, h1, l1);
                    __nv_bfloat16* p = O0 + (size_t)b * (1536 * 512) + (size_t)(h * 64 + row) * 512 + c0;
                    st_b2(p, h0, h1);
                    st_b2(p + 512 * 512, h0, h1);
                    st_b2(p + 1024 * 512, l0, l1);
                }
            } else { // EPI_WC
#pragma unroll
                for (int hrow = 0; hrow < 2; hrow++) {
                    int row = rA + hrow * 8;
                    float u0 = hrow ? v10 : v00;
                    float u1 = hrow ? v11 : v01;
                    __nv_bfloat16 h0, l0, h1, l1;
                    split2(u0, h0, l0); split2(u1, h1, l1);
                    __nv_bfloat16* p = O0 + (size_t)z * (1536 * 512) + (size_t)row * 512 + c0;
                    st_b2(p, h0, h1);
                    st_b2(p + 512 * 512, h0, h1);
                    st_b2(p + 1024 * 512, l0, l1);
                }
            }
        }
    }
}

// ---------------- LayerNorm -> bf16 split (A-format [hi|lo|hi]) ----------------
template<int DIM, bool ADDPOS, bool SWISH>
__global__ void ln_split_kernel(const float* __restrict__ in,
                                const float* __restrict__ pos,
                                const float* __restrict__ gam,
                                const float* __restrict__ bet,
                                __nv_bfloat16* __restrict__ out)
{
    constexpr int PER = DIM / 256;
    int row = blockIdx.x;
    const float* xr = in + (size_t)row * DIM;
    float v[PER];
    float s = 0.f, s2 = 0.f;
#pragma unroll
    for (int i = 0; i < PER; i++) {
        v[i] = xr[threadIdx.x + i * 256];
        s += v[i]; s2 += v[i] * v[i];
    }
    __shared__ float sh[2][8];
    int lane = threadIdx.x & 31, w = threadIdx.x >> 5;
#pragma unroll
    for (int o = 16; o > 0; o >>= 1) {
        s  += __shfl_xor_sync(0xffffffffu, s,  o);
        s2 += __shfl_xor_sync(0xffffffffu, s2, o);
    }
    if (lane == 0) { sh[0][w] = s; sh[1][w] = s2; }
    __syncthreads();
    s = 0.f; s2 = 0.f;
#pragma unroll
    for (int i = 0; i < 8; i++) { s += sh[0][i]; s2 += sh[1][i]; }
    float mu = s / (float)DIM;
    float var = s2 / (float)DIM - mu * mu;
    float rstd = rsqrtf(var + 1e-5f);
    int prow = ADDPOS ? (row % NN_) : 0;
    __nv_bfloat16* orow = out + (size_t)row * (3 * DIM);
#pragma unroll
    for (int i = 0; i < PER; i++) {
        int d = threadIdx.x + i * 256;
        float y = (v[i] - mu) * rstd * gam[d] + bet[d];
        if (ADDPOS) y += pos[(size_t)prow * DIM + d];
        if (SWISH)  y = y / (1.f + __expf(-y));
        __nv_bfloat16 hi, lo;
        split2(y, hi, lo);
        orow[d] = hi;
        orow[DIM + d] = lo;
        orow[2 * DIM + d] = hi;
    }
}

// ---------------- weight splits ----------------
__global__ void splitB_kernel(const float* __restrict__ src, int srcld, long hs,
                              __nv_bfloat16* __restrict__ dst, int K, int N, int total)
{
    int idx = blockIdx.x * blockDim.x + threadIdx.x;
    if (idx >= total) return;
    int h = idx / (K * N);
    int r = idx - h * (K * N);
    int k = r / N, n = r - k * N;
    float v = src[(size_t)h * hs + (size_t)k * srcld + n];
    __nv_bfloat16 hi, lo; split2(v, hi, lo);
    __nv_bfloat16* d = dst + (size_t)h * 3 * K * N;
    d[(size_t)k * N + n] = hi;
    d[(size_t)(K + k) * N + n] = hi;
    d[(size_t)(2 * K + k) * N + n] = lo;
}
__global__ void splitA_wv_kernel(const float* __restrict__ src,
                                 __nv_bfloat16* __restrict__ dst)
{
    int idx = blockIdx.x * blockDim.x + threadIdx.x;
    if (idx >= HH * DD * DD) return;
    int h = idx / (DD * DD);
    int r = idx - h * (DD * DD);
    int din = r / DD, vv = r - din * DD;
    float v = src[(size_t)din * QKVW + 1024 + h * DD + vv];
    __nv_bfloat16 hi, lo; split2(v, hi, lo);
    __nv_bfloat16* d = dst + (size_t)h * (DD * 3 * DD) + (size_t)din * (3 * DD);
    d[vv] = hi; d[DD + vv] = lo; d[2 * DD + vv] = hi;
}

// ---------------- launch ----------------
extern "C" void kernel_launch(void* const* d_in, const int* in_sizes, int n_in,
                              void* d_out, int out_size)
{
    const float* x       = (const float*)d_in[0];
    const float* pos     = (const float*)d_in[1];
    const float* scale   = (const float*)d_in[2];
    const float* ln0_g   = (const float*)d_in[3];
    const float* ln0_b   = (const float*)d_in[4];
    const float* W_qkv   = (const float*)d_in[5];
    const float* b_qkv   = (const float*)d_in[6];
    const float* W_merge = (const float*)d_in[7];
    const float* b_merge = (const float*)d_in[8];
    const float* ln1_g   = (const float*)d_in[9];
    const float* ln1_b   = (const float*)d_in[10];
    const float* W_ff1   = (const float*)d_in[11];
    const float* b_ff1   = (const float*)d_in[12];
    const float* ln2_g   = (const float*)d_in[13];
    const float* ln2_b   = (const float*)d_in[14];
    const float* W_ff2   = (const float*)d_in[15];
    const float* b_ff2   = (const float*)d_in[16];
    float* out = (float*)d_out;

    __nv_bfloat16 *h_e, *wqk_e, *wv_ae, *wmrg_e, *wc_e, *q_e, *k_e, *kh_e, *m2_e;
    __nv_bfloat16 *xn_e, *wff1_e, *g_e, *wff2_e;
    float *x1, *f;
    cudaGetSymbolAddress((void**)&h_e,    g_h_e);
    cudaGetSymbolAddress((void**)&wqk_e,  g_wqk_e);
    cudaGetSymbolAddress((void**)&wv_ae,  g_wv_ae);
    cudaGetSymbolAddress((void**)&wmrg_e, g_wmrg_e);
    cudaGetSymbolAddress((void**)&wc_e,   g_wc_e);
    cudaGetSymbolAddress((void**)&q_e,    g_q_e);
    cudaGetSymbolAddress((void**)&k_e,    g_k_e);
    cudaGetSymbolAddress((void**)&kh_e,   g_kh_e);
    cudaGetSymbolAddress((void**)&m2_e,   g_m2_e);
    cudaGetSymbolAddress((void**)&x1,     g_x1);
    cudaGetSymbolAddress((void**)&xn_e,   g_xn_e);
    cudaGetSymbolAddress((void**)&wff1_e, g_wff1_e);
    cudaGetSymbolAddress((void**)&f,      g_f);
    cudaGetSymbolAddress((void**)&g_e,    g_g_e);
    cudaGetSymbolAddress((void**)&wff2_e, g_wff2_e);

    cudaFuncSetAttribute((const void*)tgemm<128, EPI_F32, 0>, cudaFuncAttributeMaxDynamicSharedMemorySize, 65536);
    cudaFuncSetAttribute((const void*)tgemm<128, EPI_QK, 0>,  cudaFuncAttributeMaxDynamicSharedMemorySize, 65536);
    cudaFuncSetAttribute((const void*)tgemm<128, EPI_WC, 0>,  cudaFuncAttributeMaxDynamicSharedMemorySize, 65536);
    cudaFuncSetAttribute((const void*)tgemm<64,  EPI_KH, 1>,  cudaFuncAttributeMaxDynamicSharedMemorySize, 49152);
    cudaFuncSetAttribute((const void*)tgemm<64,  EPI_M2, 0>,  cudaFuncAttributeMaxDynamicSharedMemorySize, 49152);

    // ---- weight splits ----
    splitB_kernel<<<(DD * 1024 + 255) / 256, 256>>>(W_qkv, QKVW, 0, wqk_e, DD, 1024, DD * 1024);
    splitA_wv_kernel<<<(HH * DD * DD + 255) / 256, 256>>>(W_qkv, wv_ae);
    splitB_kernel<<<(HH * DD * DD + 255) / 256, 256>>>(W_merge, DD, (long)DD * DD, wmrg_e, DD, DD, HH * DD * DD);
    splitB_kernel<<<(DD * DEE + 255) / 256, 256>>>(W_ff1, DEE, 0, wff1_e, DD, DEE, DD * DEE);
    splitB_kernel<<<(DEE * DD + 255) / 256, 256>>>(W_ff2, DD, 0, wff2_e, DEE, DD, DEE * DD);

    // ---- Wc_h = Wv_h @ Wmrg_h  (M=512, N=512, K=1536; per head) ----
    tgemm<128, EPI_WC, 0><<<dim3(4, 4, HH), 256, 65536>>>(
        wv_ae, wmrg_e, nullptr, nullptr, nullptr, nullptr,
        wc_e, nullptr,
        3 * DD, 3 * DD, DD, 0,
        (long)DD * 3 * DD, (long)3 * DD * DD, 0, 0, 0);

    // 1) h = swish(LN0(x) + pos) -> A-format split only
    ln_split_kernel<512, true, true><<<ROWS, 256>>>(x, pos, ln0_g, ln0_b, h_e);

    // 2) qk = h @ W_qk + b_qk  (M=8192, N=1024, K=1536) -> q_e, k_e(scaled, transposed)
    tgemm<128, EPI_QK, 0><<<dim3(8, ROWS / 128, 1), 256, 65536>>>(
        h_e, wqk_e, nullptr, b_qkv, nullptr, scale,
        q_e, k_e,
        3 * DD, 3 * DD, 1024, 0, 0, 0, 0, 0, 0);

    // 3) kh[b,h] = (k^T * rs) @ h[b]  (M=64, N=512, K=3072), B read remapped from h_e
    tgemm<64, EPI_KH, 1><<<dim3(4, 1, BB * HH), 256, 49152>>>(
        k_e, h_e, nullptr, nullptr, nullptr, nullptr,
        kh_e, nullptr,
        3 * NN_, 3 * NN_, 0, 0,
        (long)DHH * 3 * NN_, (long)NN_ * 1536, 0, 0, HH);

    // 4) m2[b,h] = kh[b,h] @ Wc_h  (M=64, N=512, K=1536) -> m2_e (B-format per batch)
    tgemm<64, EPI_M2, 0><<<dim3(4, 1, BB * HH), 256, 49152>>>(
        kh_e, wc_e, nullptr, nullptr, nullptr, nullptr,
        m2_e, nullptr,
        3 * DD, 3 * DD, DD, 0,
        (long)DHH * 3 * DD, (long)3 * DD * DD, 0, HH, 0);

    // 5) x1[b] = Q[b] @ M2cat[b] + b_merge + x  (M=1024, N=512, K=1536)
    tgemm<128, EPI_F32, 0><<<dim3(4, NN_ / 128, BB), 256, 65536>>>(
        q_e, m2_e, x1, b_merge, x, nullptr,
        nullptr, nullptr,
        3 * DD, 3 * DD, DD, DD,
        (long)NN_ * 3 * DD, (long)3 * DD * DD, (long)NN_ * DD, 0, 0);

    // 6) xn_e = split(LN1(x1));  f = xn @ W_ff1 + b_ff1
    ln_split_kernel<512, false, false><<<ROWS, 256>>>(x1, nullptr, ln1_g, ln1_b, xn_e);
    tgemm<128, EPI_F32, 0><<<dim3(DEE / 128, ROWS / 128, 1), 256, 65536>>>(
        xn_e, wff1_e, f, b_ff1, nullptr, nullptr,
        nullptr, nullptr,
        3 * DD, 3 * DD, DEE, DEE, 0, 0, 0, 0, 0);

    // 7) g_e = split(swish(LN2(f)));  out = g @ W_ff2 + b_ff2 + x1
    ln_split_kernel<2048, false, true><<<ROWS, 256>>>(f, nullptr, ln2_g, ln2_b, g_e);
    tgemm<128, EPI_F32, 0><<<dim3(4, ROWS / 128, 1), 256, 65536>>>(
        g_e, wff2_e, out, b_ff2, x1, nullptr,
        nullptr, nullptr,
        3 * DEE, 3 * DEE, DD, DD, 0, 0, 0, 0, 0);
}

// round 16
// speedup vs baseline: 1.0015x; 1.0015x over previous
#include <cuda_runtime.h>
#include <cuda_bf16.h>
#include <math.h>
#include <stdint.h>

// ---------------- problem constants ----------------
#define BB   8
#define NN_  1024
#define DD   512
#define HH   8
#define DHH  64
#define DEE  2048
#define ROWS (BB*NN_)        // 8192
#define QKVW 5120

// ---------------- scratch (device globals) ----------------
__device__ __align__(128) __nv_bfloat16 g_h_e   [ROWS*3*DD];           // A-format LN0 out
__device__ __align__(128) __nv_bfloat16 g_wqk_e [3*DD*1024];           // B-format W_q|W_k
__device__ __align__(128) __nv_bfloat16 g_wv_ae [HH*DD*3*DD];          // A-format W_v per head
__device__ __align__(128) __nv_bfloat16 g_wmrg_e[HH*3*DD*DD];          // B-format W_merge per head
__device__ __align__(128) __nv_bfloat16 g_wc_e  [HH*3*DD*DD];          // B-format Wc = Wv@Wmrg per head
__device__ __align__(128) __nv_bfloat16 g_q_e   [ROWS*3*DD];           // A-format q
__device__ __align__(128) __nv_bfloat16 g_k_e   [BB*HH*DHH*3*NN_];     // A-format k^T (scaled)
__device__ __align__(128) __nv_bfloat16 g_kh_e  [BB*HH*DHH*3*DD];      // A-format kh = k^T h
__device__ __align__(128) __nv_bfloat16 g_m2_e  [BB*3*DD*DD];          // B-format M2cat per batch
__device__ __align__(128) float         g_x1    [ROWS*DD];
__device__ __align__(128) __nv_bfloat16 g_xn_e  [ROWS*3*DD];
__device__ __align__(128) __nv_bfloat16 g_wff1_e[3*DD*DEE];
__device__ __align__(128) float         g_f     [(size_t)ROWS*DEE];
__device__ __align__(128) __nv_bfloat16 g_g_e   [(size_t)ROWS*3*DEE];
__device__ __align__(128) __nv_bfloat16 g_wff2_e[3*DEE*DD];

// ---------------- helpers ----------------
__device__ __forceinline__ uint32_t smem_to_u32(const void* p) {
    uint32_t a;
    asm("{ .reg .u64 t; cvta.to.shared.u64 t, %1; cvt.u32.u64 %0, t; }" : "=r"(a) : "l"(p));
    return a;
}
#define SWZ(b) ((uint32_t)(b) ^ ((((uint32_t)(b)) >> 3) & 0x70))

#define CP_ASYNC16(dst, src) \
    asm volatile("cp.async.cg.shared.global [%0], [%1], 16;" :: "r"(dst), "l"(src) : "memory")
#define CP_COMMIT() asm volatile("cp.async.commit_group;" ::: "memory")
#define CP_WAIT1()  asm volatile("cp.async.wait_group 1;" ::: "memory")
#define CP_WAIT0()  asm volatile("cp.async.wait_group 0;" ::: "memory")

#define LDMATRIX_X4(r, addr) \
    asm volatile("ldmatrix.sync.aligned.m8n8.x4.shared.b16 {%0,%1,%2,%3}, [%4];" \
        : "=r"((r)[0]), "=r"((r)[1]), "=r"((r)[2]), "=r"((r)[3]) : "r"(addr))
#define LDMATRIX_X4_T(r, addr) \
    asm volatile("ldmatrix.sync.aligned.m8n8.x4.trans.shared.b16 {%0,%1,%2,%3}, [%4];" \
        : "=r"((r)[0]), "=r"((r)[1]), "=r"((r)[2]), "=r"((r)[3]) : "r"(addr))

#define MMA16816(c, a, b0v, b1v) \
    asm volatile("mma.sync.aligned.m16n8k16.row.col.f32.bf16.bf16.f32 " \
        "{%0,%1,%2,%3}, {%4,%5,%6,%7}, {%8,%9}, {%0,%1,%2,%3};" \
        : "+f"((c)[0]), "+f"((c)[1]), "+f"((c)[2]), "+f"((c)[3]) \
        : "r"((a)[0]), "r"((a)[1]), "r"((a)[2]), "r"((a)[3]), "r"(b0v), "r"(b1v))

__device__ __forceinline__ void split2(float v, __nv_bfloat16& h, __nv_bfloat16& l) {
    h = __float2bfloat16(v);
    l = __float2bfloat16(v - __bfloat162float(h));
}
__device__ __forceinline__ void st_b2(__nv_bfloat16* p, __nv_bfloat16 a, __nv_bfloat16 b) {
    __nv_bfloat162 t; t.x = a; t.y = b;
    *reinterpret_cast<__nv_bfloat162*>(p) = t;
}

// epilogue modes
#define EPI_F32 0
#define EPI_QK  1
#define EPI_KH  2
#define EPI_M2  3
#define EPI_WC  4

// ---------------- bf16 MMA GEMM ----------------
// BM in {128,64}; BN=128; BK=64; 8 warps. z = blockIdx.z; B batch idx = z%bmod or z/bdiv.
// BRM: remap B-source reads to A-format h_e layout ([hi|lo|hi] rows of 1536,
//      k-row kk -> h_e[(kk&1023)][ (kk>>10)==2 ? 512+d : d ]).
template<int BM, int EPI, int BRM>
__global__ void __launch_bounds__(256, 2)
tgemm(const __nv_bfloat16* __restrict__ A, const __nv_bfloat16* __restrict__ B,
      float* __restrict__ C, const float* __restrict__ bias,
      const float* __restrict__ Res, const float* __restrict__ scaleptr,
      __nv_bfloat16* __restrict__ O0, __nv_bfloat16* __restrict__ O1,
      int Kp, int lda, int ldb, int ldc,
      long bA, long bB, long bC, int bmod, int bdiv)
{
    constexpr int WMS  = BM / 32;
    constexpr int WNT  = 128 / (8 / WMS);
    constexpr int NG   = WNT / 16;
    constexpr int NT   = 2 * NG;
    constexpr int ABUF = BM * 128;

    extern __shared__ __align__(1024) char smem[];
    const uint32_t sbase = smem_to_u32(smem);
    const uint32_t sA = sbase, sB = sbase + 2 * ABUF;

    int tid = threadIdx.x, lane = tid & 31, wid = tid >> 5;
    int wm = wid % WMS, wn = wid / WMS;
    int z = blockIdx.z;
    int zB = bmod ? (z % bmod) : (bdiv ? (z / bdiv) : z);
    A += (size_t)z * bA;
    B += (size_t)zB * bB;
    int m0 = blockIdx.y * BM, n0 = blockIdx.x * 128;

    float acc[2][NT][4];
#pragma unroll
    for (int i = 0; i < 2; i++)
#pragma unroll
        for (int j = 0; j < NT; j++)
#pragma unroll
            for (int k = 0; k < 4; k++) acc[i][j][k] = 0.f;

    int nch = Kp >> 6;
    const int a_r = tid >> 3, a_c = tid & 7;

    auto load_chunk = [&](int i) {
        int buf = i & 1;
        int k0 = i << 6;
        uint32_t abuf = sA + buf * ABUF;
        uint32_t bbuf = sB + buf * 16384;
#pragma unroll
        for (int it = 0; it < BM / 32; it++) {
            int r = a_r + it * 32;
            const __nv_bfloat16* src = A + (size_t)(m0 + r) * lda + k0 + a_c * 8;
            CP_ASYNC16(abuf + SWZ(r * 128 + a_c * 16), src);
        }
#pragma unroll
        for (int it = 0; it < 4; it++) {
            int idx = tid + it * 256;
            int sub = idx >> 9, r = (idx >> 3) & 63, c = idx & 7;
            const __nv_bfloat16* src;
            if (BRM) {
                int kk = k0 + r;
                src = B + (size_t)(kk & 1023) * 1536 + ((kk >> 10) == 2 ? 512 : 0)
                        + n0 + sub * 64 + c * 8;
            } else {
                src = B + (size_t)(k0 + r) * ldb + n0 + sub * 64 + c * 8;
            }
            CP_ASYNC16(bbuf + sub * 8192 + SWZ(r * 128 + c * 16), src);
        }
        CP_COMMIT();
    };

    load_chunk(0);

    const int colsub = (wn * WNT) & 63;
    const int bsub   = (wn * WNT) >> 6;

    for (int i = 0; i < nch; i++) {
        if (i + 1 < nch) { load_chunk(i + 1); CP_WAIT1(); }
        else             { CP_WAIT0(); }
        __syncthreads();

        uint32_t abuf = sA + (i & 1) * ABUF;
        uint32_t bbuf = sB + (i & 1) * 16384 + bsub * 8192;

#pragma unroll
        for (int ks = 0; ks < 4; ks++) {
            uint32_t a[2][4];
#pragma unroll
            for (int mt = 0; mt < 2; mt++) {
                uint32_t addr = abuf +
                    SWZ((wm * 32 + mt * 16 + (lane & 15)) * 128 + ks * 32 + (lane >> 4) * 16);
                LDMATRIX_X4(a[mt], addr);
            }
            int krow = ks * 16 + (lane & 7) + ((lane >> 3) & 1) * 8;
#pragma unroll
            for (int ng = 0; ng < NG; ng++) {
                uint32_t b[4];
                int ncol = colsub + ng * 16 + (lane >> 4) * 8;
                LDMATRIX_X4_T(b, bbuf + SWZ(krow * 128 + ncol * 2));
                MMA16816(acc[0][ng * 2],     a[0], b[0], b[1]);
                MMA16816(acc[0][ng * 2 + 1], a[0], b[2], b[3]);
                MMA16816(acc[1][ng * 2],     a[1], b[0], b[1]);
                MMA16816(acc[1][ng * 2 + 1], a[1], b[2], b[3]);
            }
        }
        __syncthreads();
    }

    // ---------------- epilogue ----------------
    float rs = 1.f;
    if (EPI == EPI_QK) rs = rsqrtf(__ldg(scaleptr));

    int mbase = m0 + wm * 32 + (lane >> 2);
    int nbase = n0 + wn * WNT + (lane & 3) * 2;

#pragma unroll
    for (int mt = 0; mt < 2; mt++) {
#pragma unroll
        for (int nt = 0; nt < NT; nt++) {
            int c0 = nbase + nt * 8;
            float b0 = 0.f, b1 = 0.f;
            if (bias) { b0 = bias[c0]; b1 = bias[c0 + 1]; }
            float v00 = acc[mt][nt][0] + b0, v01 = acc[mt][nt][1] + b1;
            float v10 = acc[mt][nt][2] + b0, v11 = acc[mt][nt][3] + b1;
            int rA = mbase + mt * 16;

            if (EPI == EPI_F32) {
                if (Res) {
                    const float* R = Res + (size_t)z * bC;
                    v00 += R[(size_t)rA * ldc + c0];
                    v01 += R[(size_t)rA * ldc + c0 + 1];
                    v10 += R[(size_t)(rA + 8) * ldc + c0];
                    v11 += R[(size_t)(rA + 8) * ldc + c0 + 1];
                }
                float* Cz = C + (size_t)z * bC;
                *(float2*)&Cz[(size_t)rA * ldc + c0]       = make_float2(v00, v01);
                *(float2*)&Cz[(size_t)(rA + 8) * ldc + c0] = make_float2(v10, v11);
            } else if (EPI == EPI_QK) {
#pragma unroll
                for (int hrow = 0; hrow < 2; hrow++) {
                    int row = rA + hrow * 8;
                    float u0 = hrow ? v10 : v00;
                    float u1 = hrow ? v11 : v01;
                    if (c0 < 512) {
                        __nv_bfloat16 h0, l0, h1, l1;
                        split2(u0, h0, l0); split2(u1, h1, l1);
                        __nv_bfloat16* p = O0 + (size_t)row * 1536 + c0;
                        st_b2(p, h0, h1);
                        st_b2(p + 512, l0, l1);
                        st_b2(p + 1024, h0, h1);
                    } else {
                        u0 *= rs; u1 *= rs;
                        int cc = c0 - 512;
                        int hh = cc >> 6, m = cc & 63;
                        int b = row >> 10, ns = row & 1023;
                        __nv_bfloat16 h0, l0, h1, l1;
                        split2(u0, h0, l0); split2(u1, h1, l1);
                        __nv_bfloat16* p0 = O1 + ((size_t)(b * 8 + hh) * 64 + m) * 3072 + ns;
                        __nv_bfloat16* p1 = p0 + 3072;
                        p0[0] = h0; p0[1024] = l0; p0[2048] = h0;
                        p1[0] = h1; p1[1024] = l1; p1[2048] = h1;
                    }
                }
            } else if (EPI == EPI_KH) {
#pragma unroll
                for (int hrow = 0; hrow < 2; hrow++) {
                    int row = rA + hrow * 8;
                    float u0 = hrow ? v10 : v00;
                    float u1 = hrow ? v11 : v01;
                    __nv_bfloat16 h0, l0, h1, l1;
                    split2(u0, h0, l0); split2(u1, h1, l1);
                    __nv_bfloat16* p = O0 + ((size_t)z * 64 + row) * 1536 + c0;
                    st_b2(p, h0, h1);
                    st_b2(p + 512, l0, l1);
                    st_b2(p + 1024, h0, h1);
                }
            } else if (EPI == EPI_M2) {
                int b = z >> 3, h = z & 7;
#pragma unroll
                for (int hrow = 0; hrow < 2; hrow++) {
                    int row = rA + hrow * 8;
                    float u0 = hrow ? v10 : v00;
                    float u1 = hrow ? v11 : v01;
                    __nv_bfloat16 h0, l0, h1, l1;
                    split2(u0, h0, l0); split2(u1, h1, l1);
                    __nv_bfloat16* p = O0 + (size_t)b * (1536 * 512) + (size_t)(h * 64 + row) * 512 + c0;
                    st_b2(p, h0, h1);
                    st_b2(p + 512 * 512, h0, h1);
                    st_b2(p + 1024 * 512, l0, l1);
                }
            } else { // EPI_WC
#pragma unroll
                for (int hrow = 0; hrow < 2; hrow++) {
                    int row = rA + hrow * 8;
                    float u0 = hrow ? v10 : v00;
                    float u1 = hrow ? v11 : v01;
                    __nv_bfloat16 h0, l0, h1, l1;
                    split2(u0, h0, l0); split2(u1, h1, l1);
                    __nv_bfloat16* p = O0 + (size_t)z * (1536 * 512) + (size_t)row * 512 + c0;
                    st_b2(p, h0, h1);
                    st_b2(p + 512 * 512, h0, h1);
                    st_b2(p + 1024 * 512, l0, l1);
                }
            }
        }
    }
}

// ---------------- LayerNorm -> bf16 split (A-format [hi|lo|hi]) ----------------
template<int DIM, bool ADDPOS, bool SWISH>
__global__ void ln_split_kernel(const float* __restrict__ in,
                                const float* __restrict__ pos,
                                const float* __restrict__ gam,
                                const float* __restrict__ bet,
                                __nv_bfloat16* __restrict__ out)
{
    constexpr int PER = DIM / 256;
    int row = blockIdx.x;
    const float* xr = in + (size_t)row * DIM;
    float v[PER];
    float s = 0.f, s2 = 0.f;
#pragma unroll
    for (int i = 0; i < PER; i++) {
        v[i] = xr[threadIdx.x + i * 256];
        s += v[i]; s2 += v[i] * v[i];
    }
    __shared__ float sh[2][8];
    int lane = threadIdx.x & 31, w = threadIdx.x >> 5;
#pragma unroll
    for (int o = 16; o > 0; o >>= 1) {
        s  += __shfl_xor_sync(0xffffffffu, s,  o);
        s2 += __shfl_xor_sync(0xffffffffu, s2, o);
    }
    if (lane == 0) { sh[0][w] = s; sh[1][w] = s2; }
    __syncthreads();
    s = 0.f; s2 = 0.f;
#pragma unroll
    for (int i = 0; i < 8; i++) { s += sh[0][i]; s2 += sh[1][i]; }
    float mu = s / (float)DIM;
    float var = s2 / (float)DIM - mu * mu;
    float rstd = rsqrtf(var + 1e-5f);
    int prow = ADDPOS ? (row % NN_) : 0;
    __nv_bfloat16* orow = out + (size_t)row * (3 * DIM);
#pragma unroll
    for (int i = 0; i < PER; i++) {
        int d = threadIdx.x + i * 256;
        float y = (v[i] - mu) * rstd * gam[d] + bet[d];
        if (ADDPOS) y += pos[(size_t)prow * DIM + d];
        if (SWISH)  y = y / (1.f + __expf(-y));
        __nv_bfloat16 hi, lo;
        split2(y, hi, lo);
        orow[d] = hi;
        orow[DIM + d] = lo;
        orow[2 * DIM + d] = hi;
    }
}

// ---------------- weight splits ----------------
__global__ void splitB_kernel(const float* __restrict__ src, int srcld, long hs,
                              __nv_bfloat16* __restrict__ dst, int K, int N, int total)
{
    int idx = blockIdx.x * blockDim.x + threadIdx.x;
    if (idx >= total) return;
    int h = idx / (K * N);
    int r = idx - h * (K * N);
    int k = r / N, n = r - k * N;
    float v = src[(size_t)h * hs + (size_t)k * srcld + n];
    __nv_bfloat16 hi, lo; split2(v, hi, lo);
    __nv_bfloat16* d = dst + (size_t)h * 3 * K * N;
    d[(size_t)k * N + n] = hi;
    d[(size_t)(K + k) * N + n] = hi;
    d[(size_t)(2 * K + k) * N + n] = lo;
}
__global__ void splitA_wv_kernel(const float* __restrict__ src,
                                 __nv_bfloat16* __restrict__ dst)
{
    int idx = blockIdx.x * blockDim.x + threadIdx.x;
    if (idx >= HH * DD * DD) return;
    int h = idx / (DD * DD);
    int r = idx - h * (DD * DD);
    int din = r / DD, vv = r - din * DD;
    float v = src[(size_t)din * QKVW + 1024 + h * DD + vv];
    __nv_bfloat16 hi, lo; split2(v, hi, lo);
    __nv_bfloat16* d = dst + (size_t)h * (DD * 3 * DD) + (size_t)din * (3 * DD);
    d[vv] = hi; d[DD + vv] = lo; d[2 * DD + vv] = hi;
}

// ---------------- launch ----------------
extern "C" void kernel_launch(void* const* d_in, const int* in_sizes, int n_in,
                              void* d_out, int out_size)
{
    const float* x       = (const float*)d_in[0];
    const float* pos     = (const float*)d_in[1];
    const float* scale   = (const float*)d_in[2];
    const float* ln0_g   = (const float*)d_in[3];
    const float* ln0_b   = (const float*)d_in[4];
    const float* W_qkv   = (const float*)d_in[5];
    const float* b_qkv   = (const float*)d_in[6];
    const float* W_merge = (const float*)d_in[7];
    const float* b_merge = (const float*)d_in[8];
    const float* ln1_g   = (const float*)d_in[9];
    const float* ln1_b   = (const float*)d_in[10];
    const float* W_ff1   = (const float*)d_in[11];
    const float* b_ff1   = (const float*)d_in[12];
    const float* ln2_g   = (const float*)d_in[13];
    const float* ln2_b   = (const float*)d_in[14];
    const float* W_ff2   = (const float*)d_in[15];
    const float* b_ff2   = (const float*)d_in[16];
    float* out = (float*)d_out;

    __nv_bfloat16 *h_e, *wqk_e, *wv_ae, *wmrg_e, *wc_e, *q_e, *k_e, *kh_e, *m2_e;
    __nv_bfloat16 *xn_e, *wff1_e, *g_e, *wff2_e;
    float *x1, *f;
    cudaGetSymbolAddress((void**)&h_e,    g_h_e);
    cudaGetSymbolAddress((void**)&wqk_e,  g_wqk_e);
    cudaGetSymbolAddress((void**)&wv_ae,  g_wv_ae);
    cudaGetSymbolAddress((void**)&wmrg_e, g_wmrg_e);
    cudaGetSymbolAddress((void**)&wc_e,   g_wc_e);
    cudaGetSymbolAddress((void**)&q_e,    g_q_e);
    cudaGetSymbolAddress((void**)&k_e,    g_k_e);
    cudaGetSymbolAddress((void**)&kh_e,   g_kh_e);
    cudaGetSymbolAddress((void**)&m2_e,   g_m2_e);
    cudaGetSymbolAddress((void**)&x1,     g_x1);
    cudaGetSymbolAddress((void**)&xn_e,   g_xn_e);
    cudaGetSymbolAddress((void**)&wff1_e, g_wff1_e);
    cudaGetSymbolAddress((void**)&f,      g_f);
    cudaGetSymbolAddress((void**)&g_e,    g_g_e);
    cudaGetSymbolAddress((void**)&wff2_e, g_wff2_e);

    cudaFuncSetAttribute((const void*)tgemm<128, EPI_F32, 0>, cudaFuncAttributeMaxDynamicSharedMemorySize, 65536);
    cudaFuncSetAttribute((const void*)tgemm<128, EPI_QK, 0>,  cudaFuncAttributeMaxDynamicSharedMemorySize, 65536);
    cudaFuncSetAttribute((const void*)tgemm<128, EPI_WC, 0>,  cudaFuncAttributeMaxDynamicSharedMemorySize, 65536);
    cudaFuncSetAttribute((const void*)tgemm<64,  EPI_KH, 1>,  cudaFuncAttributeMaxDynamicSharedMemorySize, 49152);
    cudaFuncSetAttribute((const void*)tgemm<64,  EPI_M2, 0>,  cudaFuncAttributeMaxDynamicSharedMemorySize, 49152);

    // ---- weight splits ----
    splitB_kernel<<<(DD * 1024 + 255) / 256, 256>>>(W_qkv, QKVW, 0, wqk_e, DD, 1024, DD * 1024);
    splitA_wv_kernel<<<(HH * DD * DD + 255) / 256, 256>>>(W_qkv, wv_ae);
    splitB_kernel<<<(HH * DD * DD + 255) / 256, 256>>>(W_merge, DD, (long)DD * DD, wmrg_e, DD, DD, HH * DD * DD);
    splitB_kernel<<<(DD * DEE + 255) / 256, 256>>>(W_ff1, DEE, 0, wff1_e, DD, DEE, DD * DEE);
    splitB_kernel<<<(DEE * DD + 255) / 256, 256>>>(W_ff2, DD, 0, wff2_e, DEE, DD, DEE * DD);

    // ---- Wc_h = Wv_h @ Wmrg_h  (M=512, N=512, K=1536; per head) ----
    tgemm<128, EPI_WC, 0><<<dim3(4, 4, HH), 256, 65536>>>(
        wv_ae, wmrg_e, nullptr, nullptr, nullptr, nullptr,
        wc_e, nullptr,
        3 * DD, 3 * DD, DD, 0,
        (long)DD * 3 * DD, (long)3 * DD * DD, 0, 0, 0);

    // 1) h = swish(LN0(x) + pos) -> A-format split only
    ln_split_kernel<512, true, true><<<ROWS, 256>>>(x, pos, ln0_g, ln0_b, h_e);

    // 2) qk = h @ W_qk + b_qk  (M=8192, N=1024, K=1536) -> q_e, k_e(scaled, transposed)
    tgemm<128, EPI_QK, 0><<<dim3(8, ROWS / 128, 1), 256, 65536>>>(
        h_e, wqk_e, nullptr, b_qkv, nullptr, scale,
        q_e, k_e,
        3 * DD, 3 * DD, 1024, 0, 0, 0, 0, 0, 0);

    // 3) kh[b,h] = (k^T * rs) @ h[b]  (M=64, N=512, K=3072), B read remapped from h_e
    tgemm<64, EPI_KH, 1><<<dim3(4, 1, BB * HH), 256, 49152>>>(
        k_e, h_e, nullptr, nullptr, nullptr, nullptr,
        kh_e, nullptr,
        3 * NN_, 3 * NN_, 0, 0,
        (long)DHH * 3 * NN_, (long)NN_ * 1536, 0, 0, HH);

    // 4) m2[b,h] = kh[b,h] @ Wc_h  (M=64, N=512, K=1536) -> m2_e (B-format per batch)
    tgemm<64, EPI_M2, 0><<<dim3(4, 1, BB * HH), 256, 49152>>>(
        kh_e, wc_e, nullptr, nullptr, nullptr, nullptr,
        m2_e, nullptr,
        3 * DD, 3 * DD, DD, 0,
        (long)DHH * 3 * DD, (long)3 * DD * DD, 0, HH, 0);

    // 5) x1[b] = Q[b] @ M2cat[b] + b_merge + x  (M=1024, N=512, K=1536)
    tgemm<128, EPI_F32, 0><<<dim3(4, NN_ / 128, BB), 256, 65536>>>(
        q_e, m2_e, x1, b_merge, x, nullptr,
        nullptr, nullptr,
        3 * DD, 3 * DD, DD, DD,
        (long)NN_ * 3 * DD, (long)3 * DD * DD, (long)NN_ * DD, 0, 0);

    // 6) xn_e = split(LN1(x1));  f = xn @ W_ff1 + b_ff1
    ln_split_kernel<512, false, false><<<ROWS, 256>>>(x1, nullptr, ln1_g, ln1_b, xn_e);
    tgemm<128, EPI_F32, 0><<<dim3(DEE / 128, ROWS / 128, 1), 256, 65536>>>(
        xn_e, wff1_e, f, b_ff1, nullptr, nullptr,
        nullptr, nullptr,
        3 * DD, 3 * DD, DEE, DEE, 0, 0, 0, 0, 0);

    // 7) g_e = split(swish(LN2(f)));  out = g @ W_ff2 + b_ff2 + x1
    ln_split_kernel<2048, false, true><<<ROWS, 256>>>(f, nullptr, ln2_g, ln2_b, g_e);
    tgemm<128, EPI_F32, 0><<<dim3(4, ROWS / 128, 1), 256, 65536>>>(
        g_e, wff2_e, out, b_ff2, x1, nullptr,
        nullptr, nullptr,
        3 * DEE, 3 * DEE, DD, DD, 0, 0, 0, 0, 0);
}